// round 10
// baseline (speedup 1.0000x reference)
#include <cuda_runtime.h>
#include <cuda_bf16.h>
#include <math.h>
#include <stdint.h>

#define BATCH 8
#define SEQ 1024
#define DMODEL 768
#define NH 12
#define HD 64
#define ATTN_SCALE 0.125f
#define MTOT (BATCH * SEQ)         /* 8192 */
#define NQKV (3 * DMODEL)          /* 2304 */

typedef __nv_bfloat16 bf16;

// ---------------------------------------------------------------------------
// Scratch — fp32 only (proven-safe static layout)
// ---------------------------------------------------------------------------
__device__ float g_q[BATCH * NH * SEQ * HD];
__device__ float g_k[BATCH * NH * SEQ * HD];
__device__ float g_v[BATCH * NH * SEQ * HD];
__device__ float g_ctx[BATCH * NH * SEQ * HD];
__device__ float g_wqkvT[NQKV * DMODEL];      // [N][K] fp32
__device__ float g_wprojT[DMODEL * DMODEL];   // [N][K] fp32

// ---------------------------------------------------------------------------
// Helpers
// ---------------------------------------------------------------------------
__device__ __forceinline__ void mma16816(float* c, const uint32_t* a,
                                         const uint32_t* b) {
    asm volatile(
        "mma.sync.aligned.m16n8k16.row.col.f32.bf16.bf16.f32 "
        "{%0,%1,%2,%3}, {%4,%5,%6,%7}, {%8,%9}, {%0,%1,%2,%3};"
        : "+f"(c[0]), "+f"(c[1]), "+f"(c[2]), "+f"(c[3])
        : "r"(a[0]), "r"(a[1]), "r"(a[2]), "r"(a[3]), "r"(b[0]), "r"(b[1]));
}

__device__ __forceinline__ void split2(float v0, float v1,
                                       __nv_bfloat162& h, __nv_bfloat162& l) {
    bf16 h0 = __float2bfloat16(v0), h1 = __float2bfloat16(v1);
    h = __halves2bfloat162(h0, h1);
    l = __halves2bfloat162(__float2bfloat16(v0 - __bfloat162float(h0)),
                           __float2bfloat16(v1 - __bfloat162float(h1)));
}

// float2 -> packed bf16x2 hi + lo (residual) in registers
__device__ __forceinline__ void cvt_split(float2 v, uint32_t& hi, uint32_t& lo) {
    uint32_t h;
    asm("cvt.rn.bf16x2.f32 %0, %1, %2;" : "=r"(h) : "f"(v.y), "f"(v.x));
    float h0 = __uint_as_float(h << 16);
    float h1 = __uint_as_float(h & 0xFFFF0000u);
    uint32_t l;
    asm("cvt.rn.bf16x2.f32 %0, %1, %2;" : "=r"(l) : "f"(v.y - h1), "f"(v.x - h0));
    hi = h; lo = l;
}

#define CP_ASYNC16(saddr, gptr) \
    asm volatile("cp.async.cg.shared.global [%0], [%1], 16;" \
                 :: "r"(saddr), "l"(gptr) : "memory")
#define CP_COMMIT() asm volatile("cp.async.commit_group;" ::: "memory")
#define CP_WAIT_1() asm volatile("cp.async.wait_group 1;" ::: "memory")
#define CP_WAIT_0() asm volatile("cp.async.wait_group 0;" ::: "memory")

// ---------------------------------------------------------------------------
// fp32 transpose: W [K][N] -> WT [N][K]
// ---------------------------------------------------------------------------
__global__ void transpose_f32(const float* __restrict__ W,
                              float* __restrict__ WT, int N, int K)
{
    __shared__ float t[32][33];
    int n0 = blockIdx.x * 32, k0 = blockIdx.y * 32;
    int tx = threadIdx.x, ty = threadIdx.y;
#pragma unroll
    for (int i = 0; i < 4; ++i)
        t[ty + i * 8][tx] = W[(size_t)(k0 + ty + i * 8) * N + n0 + tx];
    __syncthreads();
#pragma unroll
    for (int i = 0; i < 4; ++i) {
        int n = ty + i * 8;
        WT[(size_t)(n0 + n) * K + k0 + tx] = t[tx][n];
    }
}

// ---------------------------------------------------------------------------
// Shared compute: one 32-k chunk, fp32 smem tiles (stride 40), 3-term HMMA.
// acc[2][8][4]; warp (wid&3)->32 rows, (wid>>2)->64 cols.
// ---------------------------------------------------------------------------
__device__ __forceinline__ void gemm_chunk(
    const float* __restrict__ sA, const float* __restrict__ sB,
    int wrow, int wcol, int g, int tig, float acc[2][8][4])
{
#pragma unroll
    for (int ks = 0; ks < 2; ++ks) {
        const int ko = ks * 16;
        uint32_t ah[2][4], al[2][4];
#pragma unroll
        for (int mi = 0; mi < 2; ++mi) {
            const float* p = sA + (wrow + mi * 16 + g) * 40 + ko + 2 * tig;
            cvt_split(*reinterpret_cast<const float2*>(p), ah[mi][0], al[mi][0]);
            cvt_split(*reinterpret_cast<const float2*>(p + 8 * 40), ah[mi][1], al[mi][1]);
            cvt_split(*reinterpret_cast<const float2*>(p + 8), ah[mi][2], al[mi][2]);
            cvt_split(*reinterpret_cast<const float2*>(p + 8 * 40 + 8), ah[mi][3], al[mi][3]);
        }
        uint32_t bh[8][2], bl[8][2];
#pragma unroll
        for (int ni = 0; ni < 8; ++ni) {
            const float* p = sB + (wcol + ni * 8 + g) * 40 + ko + 2 * tig;
            cvt_split(*reinterpret_cast<const float2*>(p), bh[ni][0], bl[ni][0]);
            cvt_split(*reinterpret_cast<const float2*>(p + 8), bh[ni][1], bl[ni][1]);
        }
#pragma unroll
        for (int mi = 0; mi < 2; ++mi)
#pragma unroll
            for (int ni = 0; ni < 8; ++ni) {
                mma16816(acc[mi][ni], ah[mi], bh[ni]);
                mma16816(acc[mi][ni], ah[mi], bl[ni]);
                mma16816(acc[mi][ni], al[mi], bh[ni]);
            }
    }
}

#define GEMM_DSMEM (20480 * 4)   /* 2 stages x (A 5120 + B 5120) floats */

// ---------------------------------------------------------------------------
// QKV GEMM: cp.async double-buffered, in-register split HMMA.
// A = hidden [8192][768], B = g_wqkvT [2304][768]. Scatter q/k/v + bias.
// ---------------------------------------------------------------------------
__global__ __launch_bounds__(256) void qkv_gemm_cp(
    const float* __restrict__ A, const float* __restrict__ BT,
    const float* __restrict__ bias)
{
    extern __shared__ float smf[];
    const int tid = threadIdx.x;
    const int wid = tid >> 5, lane = tid & 31;
    const int nb = blockIdx.x * 128, mb = blockIdx.y * 128;
    const int wrow = (wid & 3) * 32, wcol = (wid >> 2) * 64;
    const int g = lane >> 2, tig = lane & 3;
    const uint32_t sbase = (uint32_t)__cvta_generic_to_shared(smf);

    float acc[2][8][4];
#pragma unroll
    for (int mi = 0; mi < 2; ++mi)
#pragma unroll
        for (int ni = 0; ni < 8; ++ni)
#pragma unroll
            for (int r = 0; r < 4; ++r) acc[mi][ni][r] = 0.f;

    auto issue = [&](int stage, int kt) {
#pragma unroll
        for (int it = 0; it < 4; ++it) {
            int id = it * 256 + tid;
            int row = id >> 3, c = id & 7;
            uint32_t sa = sbase + (uint32_t)((stage * 5120 + row * 40 + c * 4) * 4);
            CP_ASYNC16(sa, &A[(size_t)(mb + row) * DMODEL + kt + c * 4]);
            uint32_t sb = sbase + (uint32_t)((10240 + stage * 5120 + row * 40 + c * 4) * 4);
            CP_ASYNC16(sb, &BT[(size_t)(nb + row) * DMODEL + kt + c * 4]);
        }
    };

    issue(0, 0);
    CP_COMMIT();
#pragma unroll 1
    for (int i = 0; i < 24; ++i) {
        if (i < 23) {
            issue((i + 1) & 1, (i + 1) * 32);
            CP_COMMIT();
            CP_WAIT_1();
        } else {
            CP_WAIT_0();
        }
        __syncthreads();
        gemm_chunk(smf + (i & 1) * 5120, smf + 10240 + (i & 1) * 5120,
                   wrow, wcol, g, tig, acc);
        __syncthreads();
    }

    // Epilogue: scatter fp32 into g_q/g_k/g_v [B,H,S,HD] + bias
#pragma unroll
    for (int mi = 0; mi < 2; ++mi)
#pragma unroll
        for (int ni = 0; ni < 8; ++ni) {
            int col = nb + wcol + ni * 8 + 2 * tig;
            int which = col / DMODEL;
            int rem = col - which * DMODEL;
            int h = rem >> 6, d = rem & 63;
            float* dst = (which == 0) ? g_q : ((which == 1) ? g_k : g_v);
            float b0 = bias[col], b1 = bias[col + 1];
#pragma unroll
            for (int half = 0; half < 2; ++half) {
                int m = mb + wrow + mi * 16 + g + half * 8;
                int bb = m >> 10, s = m & 1023;
                float2 o = make_float2(acc[mi][ni][half * 2 + 0] + b0,
                                       acc[mi][ni][half * 2 + 1] + b1);
                *reinterpret_cast<float2*>(
                    &dst[(((size_t)(bb * NH + h) * SEQ + s) * HD) + d]) = o;
            }
        }
}

// ---------------------------------------------------------------------------
// Proj GEMM: same machinery; A gathered from g_ctx [B,H,S,HD]; out + bias.
// ---------------------------------------------------------------------------
__global__ __launch_bounds__(256) void proj_gemm_cp(
    const float* __restrict__ BT, const float* __restrict__ bias,
    float* __restrict__ out)
{
    extern __shared__ float smf[];
    const int tid = threadIdx.x;
    const int wid = tid >> 5, lane = tid & 31;
    const int nb = blockIdx.x * 128, mb = blockIdx.y * 128;
    const int wrow = (wid & 3) * 32, wcol = (wid >> 2) * 64;
    const int g = lane >> 2, tig = lane & 3;
    const uint32_t sbase = (uint32_t)__cvta_generic_to_shared(smf);

    float acc[2][8][4];
#pragma unroll
    for (int mi = 0; mi < 2; ++mi)
#pragma unroll
        for (int ni = 0; ni < 8; ++ni)
#pragma unroll
            for (int r = 0; r < 4; ++r) acc[mi][ni][r] = 0.f;

    auto issue = [&](int stage, int kt) {
#pragma unroll
        for (int it = 0; it < 4; ++it) {
            int id = it * 256 + tid;
            int row = id >> 3, c = id & 7;
            int m = mb + row;
            int bb = m >> 10, s = m & 1023;
            int kg = kt + c * 4;
            int hk = kg >> 6, d = kg & 63;
            uint32_t sa = sbase + (uint32_t)((stage * 5120 + row * 40 + c * 4) * 4);
            CP_ASYNC16(sa, &g_ctx[(((size_t)(bb * NH + hk) * SEQ + s) * HD) + d]);
            uint32_t sb = sbase + (uint32_t)((10240 + stage * 5120 + row * 40 + c * 4) * 4);
            CP_ASYNC16(sb, &BT[(size_t)(nb + row) * DMODEL + kt + c * 4]);
        }
    };

    issue(0, 0);
    CP_COMMIT();
#pragma unroll 1
    for (int i = 0; i < 24; ++i) {
        if (i < 23) {
            issue((i + 1) & 1, (i + 1) * 32);
            CP_COMMIT();
            CP_WAIT_1();
        } else {
            CP_WAIT_0();
        }
        __syncthreads();
        gemm_chunk(smf + (i & 1) * 5120, smf + 10240 + (i & 1) * 5120,
                   wrow, wcol, g, tig, acc);
        __syncthreads();
    }

#pragma unroll
    for (int mi = 0; mi < 2; ++mi)
#pragma unroll
        for (int ni = 0; ni < 8; ++ni) {
            int col = nb + wcol + ni * 8 + 2 * tig;
            float b0 = bias[col], b1 = bias[col + 1];
#pragma unroll
            for (int half = 0; half < 2; ++half) {
                int row = mb + wrow + mi * 16 + g + half * 8;
                float2 o = make_float2(acc[mi][ni][half * 2 + 0] + b0,
                                       acc[mi][ni][half * 2 + 1] + b1);
                *reinterpret_cast<float2*>(&out[(size_t)row * DMODEL + col]) = o;
            }
        }
}

// ---------------------------------------------------------------------------
// Flash attention via HMMA (byte-identical to passing R9 kernel)
// ---------------------------------------------------------------------------
#define ATTN_SMEM 126976

__global__ __launch_bounds__(256) void attn_hmma()
{
    extern __shared__ char sm[];
    bf16* sQh = (bf16*)(sm + 0);
    bf16* sQl = (bf16*)(sm + 18432);
    bf16* sKVh = (bf16*)(sm + 36864);
    bf16* sKVl = (bf16*)(sm + 46080);
    float* sPt = (float*)(sm + 55296);
    uint32_t* sPh = (uint32_t*)(sm + 89088);
    uint32_t* sPl = (uint32_t*)(sm + 107520);
    float* sAlpha = (float*)(sm + 125952);
    float* sLinv = (float*)(sm + 126464);

    const int tid = threadIdx.x;
    const int wid = tid >> 5, lane = tid & 31;
    const int qb = blockIdx.x * 128;
    const int h = blockIdx.y, b = blockIdx.z;
    const size_t base = ((size_t)(b * NH + h)) * SEQ * HD;
    const float* Qg = g_q + base;
    const float* Kg = g_k + base;
    const float* Vg = g_v + base;

    const int wrow = (wid & 3) * 32;
    const int wcol = (wid >> 2) * 32;
    const int g = lane >> 2, tig = lane & 3;

#pragma unroll
    for (int it = 0; it < 8; ++it) {
        int id = it * 256 + tid;
        int row = id >> 4, c = id & 15;
        float4 v = *reinterpret_cast<const float4*>(
            &Qg[(size_t)(qb + row) * HD + c * 4]);
        __nv_bfloat162 h0, l0, h1, l1;
        split2(v.x, v.y, h0, l0);
        split2(v.z, v.w, h1, l1);
        *reinterpret_cast<__nv_bfloat162*>(&sQh[row * 72 + c * 4]) = h0;
        *reinterpret_cast<__nv_bfloat162*>(&sQh[row * 72 + c * 4 + 2]) = h1;
        *reinterpret_cast<__nv_bfloat162*>(&sQl[row * 72 + c * 4]) = l0;
        *reinterpret_cast<__nv_bfloat162*>(&sQl[row * 72 + c * 4 + 2]) = l1;
    }

    float oacc[2][4][4];
#pragma unroll
    for (int mi = 0; mi < 2; ++mi)
#pragma unroll
        for (int ni = 0; ni < 4; ++ni)
#pragma unroll
            for (int r = 0; r < 4; ++r) oacc[mi][ni][r] = 0.f;
    float m_run = -1e30f, l_run = 0.f;

    for (int kt = 0; kt < SEQ; kt += 64) {
#pragma unroll
        for (int it = 0; it < 4; ++it) {
            int id = it * 256 + tid;
            int j = id >> 4, c = id & 15;
            float4 v = *reinterpret_cast<const float4*>(
                &Kg[(size_t)(kt + j) * HD + c * 4]);
            __nv_bfloat162 h0, l0, h1, l1;
            split2(v.x, v.y, h0, l0);
            split2(v.z, v.w, h1, l1);
            *reinterpret_cast<__nv_bfloat162*>(&sKVh[j * 72 + c * 4]) = h0;
            *reinterpret_cast<__nv_bfloat162*>(&sKVh[j * 72 + c * 4 + 2]) = h1;
            *reinterpret_cast<__nv_bfloat162*>(&sKVl[j * 72 + c * 4]) = l0;
            *reinterpret_cast<__nv_bfloat162*>(&sKVl[j * 72 + c * 4 + 2]) = l1;
        }
        __syncthreads();

        float sacc[2][4][4];
#pragma unroll
        for (int mi = 0; mi < 2; ++mi)
#pragma unroll
            for (int ni = 0; ni < 4; ++ni)
#pragma unroll
                for (int r = 0; r < 4; ++r) sacc[mi][ni][r] = 0.f;

#pragma unroll
        for (int ks = 0; ks < 4; ++ks) {
            const int ko = ks * 16;
            uint32_t ah[2][4], al[2][4];
#pragma unroll
            for (int mi = 0; mi < 2; ++mi) {
                const bf16* p = sQh + (wrow + mi * 16 + g) * 72 + ko + 2 * tig;
                ah[mi][0] = *reinterpret_cast<const uint32_t*>(p);
                ah[mi][1] = *reinterpret_cast<const uint32_t*>(p + 8 * 72);
                ah[mi][2] = *reinterpret_cast<const uint32_t*>(p + 8);
                ah[mi][3] = *reinterpret_cast<const uint32_t*>(p + 8 * 72 + 8);
                const bf16* q = sQl + (wrow + mi * 16 + g) * 72 + ko + 2 * tig;
                al[mi][0] = *reinterpret_cast<const uint32_t*>(q);
                al[mi][1] = *reinterpret_cast<const uint32_t*>(q + 8 * 72);
                al[mi][2] = *reinterpret_cast<const uint32_t*>(q + 8);
                al[mi][3] = *reinterpret_cast<const uint32_t*>(q + 8 * 72 + 8);
            }
            uint32_t bhf[4][2], blf[4][2];
#pragma unroll
            for (int ni = 0; ni < 4; ++ni) {
                const bf16* p = sKVh + (wcol + ni * 8 + g) * 72 + ko + 2 * tig;
                bhf[ni][0] = *reinterpret_cast<const uint32_t*>(p);
                bhf[ni][1] = *reinterpret_cast<const uint32_t*>(p + 8);
                const bf16* q = sKVl + (wcol + ni * 8 + g) * 72 + ko + 2 * tig;
                blf[ni][0] = *reinterpret_cast<const uint32_t*>(q);
                blf[ni][1] = *reinterpret_cast<const uint32_t*>(q + 8);
            }
#pragma unroll
            for (int mi = 0; mi < 2; ++mi)
#pragma unroll
                for (int ni = 0; ni < 4; ++ni) {
                    mma16816(sacc[mi][ni], ah[mi], bhf[ni]);
                    mma16816(sacc[mi][ni], ah[mi], blf[ni]);
                    mma16816(sacc[mi][ni], al[mi], bhf[ni]);
                }
        }

#pragma unroll
        for (int mi = 0; mi < 2; ++mi)
#pragma unroll
            for (int ni = 0; ni < 4; ++ni) {
                int col = wcol + ni * 8 + 2 * tig;
                int row = wrow + mi * 16 + g;
                sPt[col * 132 + row] = sacc[mi][ni][0];
                sPt[(col + 1) * 132 + row] = sacc[mi][ni][1];
                sPt[col * 132 + row + 8] = sacc[mi][ni][2];
                sPt[(col + 1) * 132 + row + 8] = sacc[mi][ni][3];
            }
        __syncthreads();

        if (tid < 128) {
            float tmax = -1e30f;
#pragma unroll 16
            for (int j = 0; j < 64; ++j)
                tmax = fmaxf(tmax, sPt[j * 132 + tid]);
            float m_new = fmaxf(m_run, tmax * ATTN_SCALE);
            float a = __expf(m_run - m_new);
            float sum = 0.f;
#pragma unroll 8
            for (int j2 = 0; j2 < 32; ++j2) {
                float p0 = __expf(fmaf(sPt[(2 * j2) * 132 + tid], ATTN_SCALE, -m_new));
                float p1 = __expf(fmaf(sPt[(2 * j2 + 1) * 132 + tid], ATTN_SCALE, -m_new));
                sum += p0 + p1;
                __nv_bfloat162 hh, ll;
                split2(p0, p1, hh, ll);
                sPh[tid * 36 + j2] = *reinterpret_cast<uint32_t*>(&hh);
                sPl[tid * 36 + j2] = *reinterpret_cast<uint32_t*>(&ll);
            }
            l_run = fmaf(l_run, a, sum);
            m_run = m_new;
            sAlpha[tid] = a;
        } else {
            int t2 = tid - 128;
#pragma unroll
            for (int it = 0; it < 8; ++it) {
                int id = it * 128 + t2;
                int j = id >> 4, c = id & 15;
                float4 v = *reinterpret_cast<const float4*>(
                    &Vg[(size_t)(kt + j) * HD + c * 4]);
                int d = c * 4;
                bf16 h0 = __float2bfloat16(v.x), h1 = __float2bfloat16(v.y);
                bf16 h2 = __float2bfloat16(v.z), h3 = __float2bfloat16(v.w);
                sKVh[(d + 0) * 72 + j] = h0;
                sKVh[(d + 1) * 72 + j] = h1;
                sKVh[(d + 2) * 72 + j] = h2;
                sKVh[(d + 3) * 72 + j] = h3;
                sKVl[(d + 0) * 72 + j] = __float2bfloat16(v.x - __bfloat162float(h0));
                sKVl[(d + 1) * 72 + j] = __float2bfloat16(v.y - __bfloat162float(h1));
                sKVl[(d + 2) * 72 + j] = __float2bfloat16(v.z - __bfloat162float(h2));
                sKVl[(d + 3) * 72 + j] = __float2bfloat16(v.w - __bfloat162float(h3));
            }
        }
        __syncthreads();

        {
            float a0 = sAlpha[wrow + g];
            float a1 = sAlpha[wrow + g + 8];
            float a2 = sAlpha[wrow + g + 16];
            float a3 = sAlpha[wrow + g + 24];
#pragma unroll
            for (int ni = 0; ni < 4; ++ni) {
                oacc[0][ni][0] *= a0; oacc[0][ni][1] *= a0;
                oacc[0][ni][2] *= a1; oacc[0][ni][3] *= a1;
                oacc[1][ni][0] *= a2; oacc[1][ni][1] *= a2;
                oacc[1][ni][2] *= a3; oacc[1][ni][3] *= a3;
            }
        }

#pragma unroll
        for (int ks = 0; ks < 4; ++ks) {
            uint32_t pah[2][4], pal[2][4];
#pragma unroll
            for (int mi = 0; mi < 2; ++mi) {
                int bidx = (wrow + mi * 16 + g) * 36 + ks * 8 + tig;
                pah[mi][0] = sPh[bidx];
                pah[mi][1] = sPh[bidx + 8 * 36];
                pah[mi][2] = sPh[bidx + 4];
                pah[mi][3] = sPh[bidx + 8 * 36 + 4];
                pal[mi][0] = sPl[bidx];
                pal[mi][1] = sPl[bidx + 8 * 36];
                pal[mi][2] = sPl[bidx + 4];
                pal[mi][3] = sPl[bidx + 8 * 36 + 4];
            }
            uint32_t vbh[4][2], vbl[4][2];
#pragma unroll
            for (int ni = 0; ni < 4; ++ni) {
                const bf16* p = sKVh + (wcol + ni * 8 + g) * 72 + ks * 16 + 2 * tig;
                vbh[ni][0] = *reinterpret_cast<const uint32_t*>(p);
                vbh[ni][1] = *reinterpret_cast<const uint32_t*>(p + 8);
                const bf16* q = sKVl + (wcol + ni * 8 + g) * 72 + ks * 16 + 2 * tig;
                vbl[ni][0] = *reinterpret_cast<const uint32_t*>(q);
                vbl[ni][1] = *reinterpret_cast<const uint32_t*>(q + 8);
            }
#pragma unroll
            for (int mi = 0; mi < 2; ++mi)
#pragma unroll
                for (int ni = 0; ni < 4; ++ni) {
                    mma16816(oacc[mi][ni], pah[mi], vbh[ni]);
                    mma16816(oacc[mi][ni], pah[mi], vbl[ni]);
                    mma16816(oacc[mi][ni], pal[mi], vbh[ni]);
                }
        }
        __syncthreads();
    }

    if (tid < 128) sLinv[tid] = 1.f / l_run;
    __syncthreads();

    float* Og = g_ctx + base;
#pragma unroll
    for (int mi = 0; mi < 2; ++mi) {
        int r0 = wrow + mi * 16 + g;
        float inv0 = sLinv[r0], inv1 = sLinv[r0 + 8];
#pragma unroll
        for (int ni = 0; ni < 4; ++ni) {
            int col = wcol + ni * 8 + 2 * tig;
            *reinterpret_cast<float2*>(&Og[(size_t)(qb + r0) * HD + col]) =
                make_float2(oacc[mi][ni][0] * inv0, oacc[mi][ni][1] * inv0);
            *reinterpret_cast<float2*>(&Og[(size_t)(qb + r0 + 8) * HD + col]) =
                make_float2(oacc[mi][ni][2] * inv1, oacc[mi][ni][3] * inv1);
        }
    }
}

// ---------------------------------------------------------------------------
extern "C" void kernel_launch(void* const* d_in, const int* in_sizes, int n_in,
                              void* d_out, int out_size)
{
    const float* hidden = (const float*)d_in[0];
    const float* w_qkv  = (const float*)d_in[1];
    const float* b_qkv  = (const float*)d_in[2];
    const float* w_proj = (const float*)d_in[3];
    const float* b_proj = (const float*)d_in[4];
    float* out = (float*)d_out;

    cudaFuncSetAttribute(attn_hmma,
                         cudaFuncAttributeMaxDynamicSharedMemorySize, ATTN_SMEM);
    cudaFuncSetAttribute(qkv_gemm_cp,
                         cudaFuncAttributeMaxDynamicSharedMemorySize, GEMM_DSMEM);
    cudaFuncSetAttribute(proj_gemm_cp,
                         cudaFuncAttributeMaxDynamicSharedMemorySize, GEMM_DSMEM);

    transpose_f32<<<dim3(NQKV / 32, DMODEL / 32), dim3(32, 8)>>>(
        w_qkv, g_wqkvT, NQKV, DMODEL);
    transpose_f32<<<dim3(DMODEL / 32, DMODEL / 32), dim3(32, 8)>>>(
        w_proj, g_wprojT, DMODEL, DMODEL);

    qkv_gemm_cp<<<dim3(NQKV / 128, MTOT / 128), 256, GEMM_DSMEM>>>(
        hidden, g_wqkvT, b_qkv);
    attn_hmma<<<dim3(SEQ / 128, NH, BATCH), 256, ATTN_SMEM>>>();
    proj_gemm_cp<<<dim3(DMODEL / 128, MTOT / 128), 256, GEMM_DSMEM>>>(
        g_wprojT, b_proj, out);
}

// round 11
// speedup vs baseline: 3.0062x; 3.0062x over previous
#include <cuda_runtime.h>
#include <cuda_bf16.h>
#include <math.h>
#include <stdint.h>

#define BATCH 8
#define SEQ 1024
#define DMODEL 768
#define NH 12
#define HD 64
#define ATTN_SCALE 0.125f
#define MTOT (BATCH * SEQ)         /* 8192 */
#define NQKV (3 * DMODEL)          /* 2304 */

typedef __nv_bfloat16 bf16;

// ---------------------------------------------------------------------------
// Scratch — fp32 only (proven-safe static layout)
// ---------------------------------------------------------------------------
__device__ float g_q[BATCH * NH * SEQ * HD];
__device__ float g_k[BATCH * NH * SEQ * HD];
__device__ float g_v[BATCH * NH * SEQ * HD];
__device__ float g_ctx[BATCH * NH * SEQ * HD];

// ---------------------------------------------------------------------------
// HMMA helper (m16n8k16, bf16 in / fp32 accumulate)
// ---------------------------------------------------------------------------
__device__ __forceinline__ void mma16816(float* c, const uint32_t* a,
                                         const uint32_t* b) {
    asm volatile(
        "mma.sync.aligned.m16n8k16.row.col.f32.bf16.bf16.f32 "
        "{%0,%1,%2,%3}, {%4,%5,%6,%7}, {%8,%9}, {%0,%1,%2,%3};"
        : "+f"(c[0]), "+f"(c[1]), "+f"(c[2]), "+f"(c[3])
        : "r"(a[0]), "r"(a[1]), "r"(a[2]), "r"(a[3]), "r"(b[0]), "r"(b[1]));
}

__device__ __forceinline__ void split2(float v0, float v1,
                                       __nv_bfloat162& h, __nv_bfloat162& l) {
    bf16 h0 = __float2bfloat16(v0), h1 = __float2bfloat16(v1);
    h = __halves2bfloat162(h0, h1);
    l = __halves2bfloat162(__float2bfloat16(v0 - __bfloat162float(h0)),
                           __float2bfloat16(v1 - __bfloat162float(h1)));
}

// ---------------------------------------------------------------------------
// Shared HMMA compute for one staged 32-k chunk (bf16 hi/lo smem, stride 40).
// ---------------------------------------------------------------------------
__device__ __forceinline__ void hmma_chunk(
    const bf16* sAh, const bf16* sAl, const bf16* sBh, const bf16* sBl,
    int wrow, int wcol, int g, int tig, float acc[2][8][4])
{
#pragma unroll
    for (int ks = 0; ks < 2; ++ks) {
        const int ko = ks * 16;
        uint32_t ah[2][4], al[2][4];
#pragma unroll
        for (int mi = 0; mi < 2; ++mi) {
            const bf16* p = sAh + (wrow + mi * 16 + g) * 40 + ko + 2 * tig;
            ah[mi][0] = *reinterpret_cast<const uint32_t*>(p);
            ah[mi][1] = *reinterpret_cast<const uint32_t*>(p + 8 * 40);
            ah[mi][2] = *reinterpret_cast<const uint32_t*>(p + 8);
            ah[mi][3] = *reinterpret_cast<const uint32_t*>(p + 8 * 40 + 8);
            const bf16* q = sAl + (wrow + mi * 16 + g) * 40 + ko + 2 * tig;
            al[mi][0] = *reinterpret_cast<const uint32_t*>(q);
            al[mi][1] = *reinterpret_cast<const uint32_t*>(q + 8 * 40);
            al[mi][2] = *reinterpret_cast<const uint32_t*>(q + 8);
            al[mi][3] = *reinterpret_cast<const uint32_t*>(q + 8 * 40 + 8);
        }
        uint32_t bhf[8][2], blf[8][2];
#pragma unroll
        for (int ni = 0; ni < 8; ++ni) {
            const bf16* p = sBh + (wcol + ni * 8 + g) * 40 + ko + 2 * tig;
            bhf[ni][0] = *reinterpret_cast<const uint32_t*>(p);
            bhf[ni][1] = *reinterpret_cast<const uint32_t*>(p + 8);
            const bf16* q = sBl + (wcol + ni * 8 + g) * 40 + ko + 2 * tig;
            blf[ni][0] = *reinterpret_cast<const uint32_t*>(q);
            blf[ni][1] = *reinterpret_cast<const uint32_t*>(q + 8);
        }
#pragma unroll
        for (int mi = 0; mi < 2; ++mi)
#pragma unroll
            for (int ni = 0; ni < 8; ++ni) {
                mma16816(acc[mi][ni], ah[mi], bhf[ni]);
                mma16816(acc[mi][ni], ah[mi], blf[ni]);
                mma16816(acc[mi][ni], al[mi], bhf[ni]);
            }
    }
}

// Stage prefetched registers into split smem (A natural, B transposed)
__device__ __forceinline__ void stage_chunk(
    bf16* sAh, bf16* sAl, bf16* sBh, bf16* sBl,
    const float4* ra, const float4* rb, int tid)
{
#pragma unroll
    for (int it = 0; it < 4; ++it) {
        int id = it * 256 + tid;
        {
            int row = id >> 3, c = id & 7;
            float4 v = ra[it];
            bf16 h0 = __float2bfloat16(v.x), h1 = __float2bfloat16(v.y);
            bf16 h2 = __float2bfloat16(v.z), h3 = __float2bfloat16(v.w);
            int o = row * 40 + c * 4;
            sAh[o + 0] = h0; sAh[o + 1] = h1; sAh[o + 2] = h2; sAh[o + 3] = h3;
            sAl[o + 0] = __float2bfloat16(v.x - __bfloat162float(h0));
            sAl[o + 1] = __float2bfloat16(v.y - __bfloat162float(h1));
            sAl[o + 2] = __float2bfloat16(v.z - __bfloat162float(h2));
            sAl[o + 3] = __float2bfloat16(v.w - __bfloat162float(h3));
        }
        {
            int k = id >> 5, c = id & 31;
            float4 v = rb[it];
            bf16 h0 = __float2bfloat16(v.x), h1 = __float2bfloat16(v.y);
            bf16 h2 = __float2bfloat16(v.z), h3 = __float2bfloat16(v.w);
            int n = c * 4;
            sBh[(n + 0) * 40 + k] = h0;
            sBh[(n + 1) * 40 + k] = h1;
            sBh[(n + 2) * 40 + k] = h2;
            sBh[(n + 3) * 40 + k] = h3;
            sBl[(n + 0) * 40 + k] = __float2bfloat16(v.x - __bfloat162float(h0));
            sBl[(n + 1) * 40 + k] = __float2bfloat16(v.y - __bfloat162float(h1));
            sBl[(n + 2) * 40 + k] = __float2bfloat16(v.z - __bfloat162float(h2));
            sBl[(n + 3) * 40 + k] = __float2bfloat16(v.w - __bfloat162float(h3));
        }
    }
}

// ---------------------------------------------------------------------------
// QKV GEMM: HMMA with register-prefetch double buffering.
// ---------------------------------------------------------------------------
__global__ __launch_bounds__(256) void qkv_gemm_hmma(
    const float* __restrict__ A, const float* __restrict__ W,
    const float* __restrict__ bias)
{
    __shared__ bf16 smem[512 * 40];
    bf16* sAh = smem;
    bf16* sAl = smem + 128 * 40;
    bf16* sBh = smem + 256 * 40;
    bf16* sBl = smem + 384 * 40;

    const int tid = threadIdx.x;
    const int wid = tid >> 5, lane = tid & 31;
    const int nb = blockIdx.x * 128, mb = blockIdx.y * 128;
    const int wrow = (wid & 3) * 32;
    const int wcol = (wid >> 2) * 64;
    const int g = lane >> 2, tig = lane & 3;

    float acc[2][8][4];
#pragma unroll
    for (int mi = 0; mi < 2; ++mi)
#pragma unroll
        for (int ni = 0; ni < 8; ++ni)
#pragma unroll
            for (int r = 0; r < 4; ++r) acc[mi][ni][r] = 0.f;

    float4 ra[4], rb[4];
    auto ldchunk = [&](int kt) {
#pragma unroll
        for (int it = 0; it < 4; ++it) {
            int id = it * 256 + tid;
            int row = id >> 3, c = id & 7;
            ra[it] = *reinterpret_cast<const float4*>(
                &A[(size_t)(mb + row) * DMODEL + kt + c * 4]);
            int k = id >> 5, cc = id & 31;
            rb[it] = *reinterpret_cast<const float4*>(
                &W[(size_t)(kt + k) * NQKV + nb + cc * 4]);
        }
    };

    ldchunk(0);
#pragma unroll 1
    for (int i = 0; i < 24; ++i) {
        stage_chunk(sAh, sAl, sBh, sBl, ra, rb, tid);
        __syncthreads();
        if (i < 23) ldchunk((i + 1) * 32);    // overlaps with MMA below
        hmma_chunk(sAh, sAl, sBh, sBl, wrow, wcol, g, tig, acc);
        __syncthreads();
    }

    // Epilogue: scatter fp32 into g_q/g_k/g_v [B,H,S,HD] + bias
#pragma unroll
    for (int mi = 0; mi < 2; ++mi)
#pragma unroll
        for (int ni = 0; ni < 8; ++ni) {
            int col = nb + wcol + ni * 8 + 2 * tig;
            int which = col / DMODEL;
            int rem = col - which * DMODEL;
            int h = rem >> 6, d = rem & 63;
            float* dst = (which == 0) ? g_q : ((which == 1) ? g_k : g_v);
            float b0 = bias[col], b1 = bias[col + 1];
#pragma unroll
            for (int half = 0; half < 2; ++half) {
                int m = mb + wrow + mi * 16 + g + half * 8;
                int bb = m >> 10, s = m & 1023;
                float2 o = make_float2(acc[mi][ni][half * 2 + 0] + b0,
                                       acc[mi][ni][half * 2 + 1] + b1);
                *reinterpret_cast<float2*>(
                    &dst[(((size_t)(bb * NH + h) * SEQ + s) * HD) + d]) = o;
            }
        }
}

// ---------------------------------------------------------------------------
// Proj GEMM: same machinery; A gathered from g_ctx, W transposed at staging.
// ---------------------------------------------------------------------------
__global__ __launch_bounds__(256) void proj_gemm_hmma(
    const float* __restrict__ W, const float* __restrict__ bias,
    float* __restrict__ out)
{
    __shared__ bf16 smem[512 * 40];
    bf16* sAh = smem;
    bf16* sAl = smem + 128 * 40;
    bf16* sBh = smem + 256 * 40;
    bf16* sBl = smem + 384 * 40;

    const int tid = threadIdx.x;
    const int wid = tid >> 5, lane = tid & 31;
    const int nb = blockIdx.x * 128, mb = blockIdx.y * 128;
    const int wrow = (wid & 3) * 32;
    const int wcol = (wid >> 2) * 64;
    const int g = lane >> 2, tig = lane & 3;

    float acc[2][8][4];
#pragma unroll
    for (int mi = 0; mi < 2; ++mi)
#pragma unroll
        for (int ni = 0; ni < 8; ++ni)
#pragma unroll
            for (int r = 0; r < 4; ++r) acc[mi][ni][r] = 0.f;

    float4 ra[4], rb[4];
    auto ldchunk = [&](int kt) {
#pragma unroll
        for (int it = 0; it < 4; ++it) {
            int id = it * 256 + tid;
            int row = id >> 3, c = id & 7;
            int m = mb + row;
            int bb = m >> 10, s = m & 1023;
            int kg = kt + c * 4;
            int hk = kg >> 6, d = kg & 63;
            ra[it] = *reinterpret_cast<const float4*>(
                &g_ctx[(((size_t)(bb * NH + hk) * SEQ + s) * HD) + d]);
            int k = id >> 5, cc = id & 31;
            rb[it] = *reinterpret_cast<const float4*>(
                &W[(size_t)(kt + k) * DMODEL + nb + cc * 4]);
        }
    };

    ldchunk(0);
#pragma unroll 1
    for (int i = 0; i < 24; ++i) {
        stage_chunk(sAh, sAl, sBh, sBl, ra, rb, tid);
        __syncthreads();
        if (i < 23) ldchunk((i + 1) * 32);
        hmma_chunk(sAh, sAl, sBh, sBl, wrow, wcol, g, tig, acc);
        __syncthreads();
    }

#pragma unroll
    for (int mi = 0; mi < 2; ++mi)
#pragma unroll
        for (int ni = 0; ni < 8; ++ni) {
            int col = nb + wcol + ni * 8 + 2 * tig;
            float b0 = bias[col], b1 = bias[col + 1];
#pragma unroll
            for (int half = 0; half < 2; ++half) {
                int row = mb + wrow + mi * 16 + g + half * 8;
                float2 o = make_float2(acc[mi][ni][half * 2 + 0] + b0,
                                       acc[mi][ni][half * 2 + 1] + b1);
                *reinterpret_cast<float2*>(&out[(size_t)row * DMODEL + col]) = o;
            }
        }
}

// ---------------------------------------------------------------------------
// Flash attention via HMMA (byte-identical to passing R9 kernel)
// ---------------------------------------------------------------------------
#define ATTN_SMEM 126976

__global__ __launch_bounds__(256) void attn_hmma()
{
    extern __shared__ char sm[];
    bf16* sQh = (bf16*)(sm + 0);
    bf16* sQl = (bf16*)(sm + 18432);
    bf16* sKVh = (bf16*)(sm + 36864);
    bf16* sKVl = (bf16*)(sm + 46080);
    float* sPt = (float*)(sm + 55296);
    uint32_t* sPh = (uint32_t*)(sm + 89088);
    uint32_t* sPl = (uint32_t*)(sm + 107520);
    float* sAlpha = (float*)(sm + 125952);
    float* sLinv = (float*)(sm + 126464);

    const int tid = threadIdx.x;
    const int wid = tid >> 5, lane = tid & 31;
    const int qb = blockIdx.x * 128;
    const int h = blockIdx.y, b = blockIdx.z;
    const size_t base = ((size_t)(b * NH + h)) * SEQ * HD;
    const float* Qg = g_q + base;
    const float* Kg = g_k + base;
    const float* Vg = g_v + base;

    const int wrow = (wid & 3) * 32;
    const int wcol = (wid >> 2) * 32;
    const int g = lane >> 2, tig = lane & 3;

#pragma unroll
    for (int it = 0; it < 8; ++it) {
        int id = it * 256 + tid;
        int row = id >> 4, c = id & 15;
        float4 v = *reinterpret_cast<const float4*>(
            &Qg[(size_t)(qb + row) * HD + c * 4]);
        __nv_bfloat162 h0, l0, h1, l1;
        split2(v.x, v.y, h0, l0);
        split2(v.z, v.w, h1, l1);
        *reinterpret_cast<__nv_bfloat162*>(&sQh[row * 72 + c * 4]) = h0;
        *reinterpret_cast<__nv_bfloat162*>(&sQh[row * 72 + c * 4 + 2]) = h1;
        *reinterpret_cast<__nv_bfloat162*>(&sQl[row * 72 + c * 4]) = l0;
        *reinterpret_cast<__nv_bfloat162*>(&sQl[row * 72 + c * 4 + 2]) = l1;
    }

    float oacc[2][4][4];
#pragma unroll
    for (int mi = 0; mi < 2; ++mi)
#pragma unroll
        for (int ni = 0; ni < 4; ++ni)
#pragma unroll
            for (int r = 0; r < 4; ++r) oacc[mi][ni][r] = 0.f;
    float m_run = -1e30f, l_run = 0.f;

    for (int kt = 0; kt < SEQ; kt += 64) {
#pragma unroll
        for (int it = 0; it < 4; ++it) {
            int id = it * 256 + tid;
            int j = id >> 4, c = id & 15;
            float4 v = *reinterpret_cast<const float4*>(
                &Kg[(size_t)(kt + j) * HD + c * 4]);
            __nv_bfloat162 h0, l0, h1, l1;
            split2(v.x, v.y, h0, l0);
            split2(v.z, v.w, h1, l1);
            *reinterpret_cast<__nv_bfloat162*>(&sKVh[j * 72 + c * 4]) = h0;
            *reinterpret_cast<__nv_bfloat162*>(&sKVh[j * 72 + c * 4 + 2]) = h1;
            *reinterpret_cast<__nv_bfloat162*>(&sKVl[j * 72 + c * 4]) = l0;
            *reinterpret_cast<__nv_bfloat162*>(&sKVl[j * 72 + c * 4 + 2]) = l1;
        }
        __syncthreads();

        float sacc[2][4][4];
#pragma unroll
        for (int mi = 0; mi < 2; ++mi)
#pragma unroll
            for (int ni = 0; ni < 4; ++ni)
#pragma unroll
                for (int r = 0; r < 4; ++r) sacc[mi][ni][r] = 0.f;

#pragma unroll
        for (int ks = 0; ks < 4; ++ks) {
            const int ko = ks * 16;
            uint32_t ah[2][4], al[2][4];
#pragma unroll
            for (int mi = 0; mi < 2; ++mi) {
                const bf16* p = sQh + (wrow + mi * 16 + g) * 72 + ko + 2 * tig;
                ah[mi][0] = *reinterpret_cast<const uint32_t*>(p);
                ah[mi][1] = *reinterpret_cast<const uint32_t*>(p + 8 * 72);
                ah[mi][2] = *reinterpret_cast<const uint32_t*>(p + 8);
                ah[mi][3] = *reinterpret_cast<const uint32_t*>(p + 8 * 72 + 8);
                const bf16* q = sQl + (wrow + mi * 16 + g) * 72 + ko + 2 * tig;
                al[mi][0] = *reinterpret_cast<const uint32_t*>(q);
                al[mi][1] = *reinterpret_cast<const uint32_t*>(q + 8 * 72);
                al[mi][2] = *reinterpret_cast<const uint32_t*>(q + 8);
                al[mi][3] = *reinterpret_cast<const uint32_t*>(q + 8 * 72 + 8);
            }
            uint32_t bhf[4][2], blf[4][2];
#pragma unroll
            for (int ni = 0; ni < 4; ++ni) {
                const bf16* p = sKVh + (wcol + ni * 8 + g) * 72 + ko + 2 * tig;
                bhf[ni][0] = *reinterpret_cast<const uint32_t*>(p);
                bhf[ni][1] = *reinterpret_cast<const uint32_t*>(p + 8);
                const bf16* q = sKVl + (wcol + ni * 8 + g) * 72 + ko + 2 * tig;
                blf[ni][0] = *reinterpret_cast<const uint32_t*>(q);
                blf[ni][1] = *reinterpret_cast<const uint32_t*>(q + 8);
            }
#pragma unroll
            for (int mi = 0; mi < 2; ++mi)
#pragma unroll
                for (int ni = 0; ni < 4; ++ni) {
                    mma16816(sacc[mi][ni], ah[mi], bhf[ni]);
                    mma16816(sacc[mi][ni], ah[mi], blf[ni]);
                    mma16816(sacc[mi][ni], al[mi], bhf[ni]);
                }
        }

#pragma unroll
        for (int mi = 0; mi < 2; ++mi)
#pragma unroll
            for (int ni = 0; ni < 4; ++ni) {
                int col = wcol + ni * 8 + 2 * tig;
                int row = wrow + mi * 16 + g;
                sPt[col * 132 + row] = sacc[mi][ni][0];
                sPt[(col + 1) * 132 + row] = sacc[mi][ni][1];
                sPt[col * 132 + row + 8] = sacc[mi][ni][2];
                sPt[(col + 1) * 132 + row + 8] = sacc[mi][ni][3];
            }
        __syncthreads();

        if (tid < 128) {
            float tmax = -1e30f;
#pragma unroll 16
            for (int j = 0; j < 64; ++j)
                tmax = fmaxf(tmax, sPt[j * 132 + tid]);
            float m_new = fmaxf(m_run, tmax * ATTN_SCALE);
            float a = __expf(m_run - m_new);
            float sum = 0.f;
#pragma unroll 8
            for (int j2 = 0; j2 < 32; ++j2) {
                float p0 = __expf(fmaf(sPt[(2 * j2) * 132 + tid], ATTN_SCALE, -m_new));
                float p1 = __expf(fmaf(sPt[(2 * j2 + 1) * 132 + tid], ATTN_SCALE, -m_new));
                sum += p0 + p1;
                __nv_bfloat162 hh, ll;
                split2(p0, p1, hh, ll);
                sPh[tid * 36 + j2] = *reinterpret_cast<uint32_t*>(&hh);
                sPl[tid * 36 + j2] = *reinterpret_cast<uint32_t*>(&ll);
            }
            l_run = fmaf(l_run, a, sum);
            m_run = m_new;
            sAlpha[tid] = a;
        } else {
            int t2 = tid - 128;
#pragma unroll
            for (int it = 0; it < 8; ++it) {
                int id = it * 128 + t2;
                int j = id >> 4, c = id & 15;
                float4 v = *reinterpret_cast<const float4*>(
                    &Vg[(size_t)(kt + j) * HD + c * 4]);
                int d = c * 4;
                bf16 h0 = __float2bfloat16(v.x), h1 = __float2bfloat16(v.y);
                bf16 h2 = __float2bfloat16(v.z), h3 = __float2bfloat16(v.w);
                sKVh[(d + 0) * 72 + j] = h0;
                sKVh[(d + 1) * 72 + j] = h1;
                sKVh[(d + 2) * 72 + j] = h2;
                sKVh[(d + 3) * 72 + j] = h3;
                sKVl[(d + 0) * 72 + j] = __float2bfloat16(v.x - __bfloat162float(h0));
                sKVl[(d + 1) * 72 + j] = __float2bfloat16(v.y - __bfloat162float(h1));
                sKVl[(d + 2) * 72 + j] = __float2bfloat16(v.z - __bfloat162float(h2));
                sKVl[(d + 3) * 72 + j] = __float2bfloat16(v.w - __bfloat162float(h3));
            }
        }
        __syncthreads();

        {
            float a0 = sAlpha[wrow + g];
            float a1 = sAlpha[wrow + g + 8];
            float a2 = sAlpha[wrow + g + 16];
            float a3 = sAlpha[wrow + g + 24];
#pragma unroll
            for (int ni = 0; ni < 4; ++ni) {
                oacc[0][ni][0] *= a0; oacc[0][ni][1] *= a0;
                oacc[0][ni][2] *= a1; oacc[0][ni][3] *= a1;
                oacc[1][ni][0] *= a2; oacc[1][ni][1] *= a2;
                oacc[1][ni][2] *= a3; oacc[1][ni][3] *= a3;
            }
        }

#pragma unroll
        for (int ks = 0; ks < 4; ++ks) {
            uint32_t pah[2][4], pal[2][4];
#pragma unroll
            for (int mi = 0; mi < 2; ++mi) {
                int bidx = (wrow + mi * 16 + g) * 36 + ks * 8 + tig;
                pah[mi][0] = sPh[bidx];
                pah[mi][1] = sPh[bidx + 8 * 36];
                pah[mi][2] = sPh[bidx + 4];
                pah[mi][3] = sPh[bidx + 8 * 36 + 4];
                pal[mi][0] = sPl[bidx];
                pal[mi][1] = sPl[bidx + 8 * 36];
                pal[mi][2] = sPl[bidx + 4];
                pal[mi][3] = sPl[bidx + 8 * 36 + 4];
            }
            uint32_t vbh[4][2], vbl[4][2];
#pragma unroll
            for (int ni = 0; ni < 4; ++ni) {
                const bf16* p = sKVh + (wcol + ni * 8 + g) * 72 + ks * 16 + 2 * tig;
                vbh[ni][0] = *reinterpret_cast<const uint32_t*>(p);
                vbh[ni][1] = *reinterpret_cast<const uint32_t*>(p + 8);
                const bf16* q = sKVl + (wcol + ni * 8 + g) * 72 + ks * 16 + 2 * tig;
                vbl[ni][0] = *reinterpret_cast<const uint32_t*>(q);
                vbl[ni][1] = *reinterpret_cast<const uint32_t*>(q + 8);
            }
#pragma unroll
            for (int mi = 0; mi < 2; ++mi)
#pragma unroll
                for (int ni = 0; ni < 4; ++ni) {
                    mma16816(oacc[mi][ni], pah[mi], vbh[ni]);
                    mma16816(oacc[mi][ni], pah[mi], vbl[ni]);
                    mma16816(oacc[mi][ni], pal[mi], vbh[ni]);
                }
        }
        __syncthreads();
    }

    if (tid < 128) sLinv[tid] = 1.f / l_run;
    __syncthreads();

    float* Og = g_ctx + base;
#pragma unroll
    for (int mi = 0; mi < 2; ++mi) {
        int r0 = wrow + mi * 16 + g;
        float inv0 = sLinv[r0], inv1 = sLinv[r0 + 8];
#pragma unroll
        for (int ni = 0; ni < 4; ++ni) {
            int col = wcol + ni * 8 + 2 * tig;
            *reinterpret_cast<float2*>(&Og[(size_t)(qb + r0) * HD + col]) =
                make_float2(oacc[mi][ni][0] * inv0, oacc[mi][ni][1] * inv0);
            *reinterpret_cast<float2*>(&Og[(size_t)(qb + r0 + 8) * HD + col]) =
                make_float2(oacc[mi][ni][2] * inv1, oacc[mi][ni][3] * inv1);
        }
    }
}

// ---------------------------------------------------------------------------
extern "C" void kernel_launch(void* const* d_in, const int* in_sizes, int n_in,
                              void* d_out, int out_size)
{
    const float* hidden = (const float*)d_in[0];
    const float* w_qkv  = (const float*)d_in[1];
    const float* b_qkv  = (const float*)d_in[2];
    const float* w_proj = (const float*)d_in[3];
    const float* b_proj = (const float*)d_in[4];
    float* out = (float*)d_out;

    cudaFuncSetAttribute(attn_hmma,
                         cudaFuncAttributeMaxDynamicSharedMemorySize, ATTN_SMEM);

    qkv_gemm_hmma<<<dim3(NQKV / 128, MTOT / 128), 256>>>(hidden, w_qkv, b_qkv);
    attn_hmma<<<dim3(SEQ / 128, NH, BATCH), 256, ATTN_SMEM>>>();
    proj_gemm_hmma<<<dim3(DMODEL / 128, MTOT / 128), 256>>>(
        w_proj, b_proj, out);
}